// round 7
// baseline (speedup 1.0000x reference)
#include <cuda_runtime.h>
#include <math.h>
#include <stdint.h>

#define BB 2
#define TT 2048
#define DMODEL 1024
#define NH 16
#define DK 64
#define MROWS (BB * TT)   // 4096

// ---- scratch (static device memory; no allocations allowed) ----
__device__ float g_q[(size_t)BB * NH * TT * DK];
__device__ float g_k[(size_t)BB * NH * TT * DK];
__device__ float g_v[(size_t)BB * NH * TT * DK];
__device__ float g_attn[(size_t)MROWS * DMODEL];
__device__ float g_cos[TT * 32];
__device__ float g_sin[TT * 32];

// ---------------------------------------------------------------------------
__device__ __forceinline__ float f2tf32(float x) {
    float y;
    asm("cvt.rna.tf32.f32 %0, %1;" : "=f"(y) : "f"(x));
    return y;
}

__device__ __forceinline__ void mma_tf32(float c[4],
                                         const uint32_t a[4],
                                         uint32_t b0, uint32_t b1) {
    asm volatile(
        "mma.sync.aligned.m16n8k8.row.col.f32.tf32.tf32.f32 "
        "{%0,%1,%2,%3}, {%4,%5,%6,%7}, {%8,%9}, {%0,%1,%2,%3};"
        : "+f"(c[0]), "+f"(c[1]), "+f"(c[2]), "+f"(c[3])
        : "r"(a[0]), "r"(a[1]), "r"(a[2]), "r"(a[3]), "r"(b0), "r"(b1));
}

#define CP_ASYNC16(dst, src) \
    asm volatile("cp.async.cg.shared.global [%0], [%1], 16;" :: "r"(dst), "l"(src))
#define CP_COMMIT() asm volatile("cp.async.commit_group;")
#define CP_WAIT0()  asm volatile("cp.async.wait_group 0;")

// ---------------------------------------------------------------------------
// RoPE tables + apply. rope_apply now also:
//   - pre-scales Q by 0.125*log2(e) (softmax uses exp2)
//   - converts Q and K to TF32 (flash consumes raw bits, no CVT there)
// ---------------------------------------------------------------------------
__global__ void rope_table_kernel() {
    int i = blockIdx.x * blockDim.x + threadIdx.x;
    if (i >= TT * 32) return;
    int t = i >> 5, j = i & 31;
    double inv = pow(10000.0, -((double)(2 * j)) / 64.0);
    float angf = (float)t * (float)inv;
    g_cos[i] = (float)cos((double)angf);
    g_sin[i] = (float)sin((double)angf);
}

__global__ void rope_apply_kernel() {
    int i = blockIdx.x * blockDim.x + threadIdx.x;
    const int per = BB * NH * TT * 32;
    if (i >= 2 * per) return;
    const bool isq = (i < per);
    float* arr = isq ? g_q : g_k;
    const float sc = isq ? (0.125f * 1.4426950408889634f) : 1.0f;
    int p = i & (per - 1);
    int j = p & 31;
    int bht = p >> 5;
    int t = bht & (TT - 1);
    float c = g_cos[t * 32 + j];
    float s = g_sin[t * 32 + j];
    size_t base = (size_t)bht * DK + 2 * j;
    float x1 = arr[base], x2 = arr[base + 1];
    arr[base]     = f2tf32((c * x1 - s * x2) * sc);
    arr[base + 1] = f2tf32((s * x1 + c * x2) * sc);
}

// ---------------------------------------------------------------------------
// TF32 raw-mma SGEMM, software-pipelined (register staging + double smem buf).
// MODE 0: A=x, W={Wq,Wk,Wv}, scatter into g_q/g_k/g_v [b][h][t][d];
//         V segment converted to TF32 at the epilogue (flash reads raw bits).
// MODE 1: A=g_attn, W=Wo, C=out row-major
// ---------------------------------------------------------------------------
#define LDA 36
#define GEMM_BUF (128 * LDA)
#define GEMM_SMEM (4 * GEMM_BUF * 4)

template <int MODE>
__global__ void __launch_bounds__(256, 2) gemm_mma_kernel(
    const float* __restrict__ A_,
    const float* __restrict__ W0,
    const float* __restrict__ W1,
    const float* __restrict__ W2,
    float* __restrict__ Cout)
{
    extern __shared__ float gsm[];

    const int tid = threadIdx.x;
    const int warp = tid >> 5;
    const int lane = tid & 31;
    const int g = lane >> 2;
    const int t = lane & 3;
    const int wm = warp >> 1;
    const int wn = warp & 1;
    const int mb = blockIdx.x * 128;
    const int nb = blockIdx.y * 128;

    const float* Ap = (MODE == 0) ? A_ : g_attn;
    const float* Wp;
    int nloc;
    if (MODE == 0) {
        int w = nb >> 10;
        Wp = (w == 0) ? W0 : ((w == 1) ? W1 : W2);
        nloc = nb & 1023;
    } else {
        Wp = W0;
        nloc = nb;
    }

    const int lrow = tid >> 3;
    const int lkq  = (tid & 7) << 2;

    float4 stA[4], stB[4];

#pragma unroll
    for (int i = 0; i < 4; i++) {
        int row = lrow + 32 * i;
        stA[i] = *(const float4*)(Ap + (size_t)(mb + row) * 1024 + lkq);
        stB[i] = *(const float4*)(Wp + (size_t)(nloc + row) * 1024 + lkq);
    }
    {
        float* As = gsm;
        float* Bs = gsm + GEMM_BUF;
#pragma unroll
        for (int i = 0; i < 4; i++) {
            int row = lrow + 32 * i;
            As[row * LDA + lkq + 0] = f2tf32(stA[i].x);
            As[row * LDA + lkq + 1] = f2tf32(stA[i].y);
            As[row * LDA + lkq + 2] = f2tf32(stA[i].z);
            As[row * LDA + lkq + 3] = f2tf32(stA[i].w);
            Bs[row * LDA + lkq + 0] = f2tf32(stB[i].x);
            Bs[row * LDA + lkq + 1] = f2tf32(stB[i].y);
            Bs[row * LDA + lkq + 2] = f2tf32(stB[i].z);
            Bs[row * LDA + lkq + 3] = f2tf32(stB[i].w);
        }
    }
    __syncthreads();

    float c[2][8][4];
#pragma unroll
    for (int i = 0; i < 2; i++)
#pragma unroll
        for (int nt = 0; nt < 8; nt++)
#pragma unroll
            for (int e = 0; e < 4; e++) c[i][nt][e] = 0.f;

    for (int kt = 0; kt < 32; kt++) {
        if (kt + 1 < 32) {
            int kb = (kt + 1) * 32;
#pragma unroll
            for (int i = 0; i < 4; i++) {
                int row = lrow + 32 * i;
                stA[i] = *(const float4*)(Ap + (size_t)(mb + row) * 1024 + kb + lkq);
                stB[i] = *(const float4*)(Wp + (size_t)(nloc + row) * 1024 + kb + lkq);
            }
        }

        const float* As = gsm + (kt & 1) * 2 * GEMM_BUF;
        const float* Bs = As + GEMM_BUF;

#pragma unroll
        for (int k0 = 0; k0 < 32; k0 += 8) {
            uint32_t af[2][4];
#pragma unroll
            for (int i = 0; i < 2; i++) {
                int m0 = wm * 32 + i * 16;
                af[i][0] = __float_as_uint(As[(m0 + g) * LDA + k0 + t]);
                af[i][1] = __float_as_uint(As[(m0 + g + 8) * LDA + k0 + t]);
                af[i][2] = __float_as_uint(As[(m0 + g) * LDA + k0 + t + 4]);
                af[i][3] = __float_as_uint(As[(m0 + g + 8) * LDA + k0 + t + 4]);
            }
#pragma unroll
            for (int nt = 0; nt < 8; nt++) {
                int n0 = wn * 64 + nt * 8;
                uint32_t b0 = __float_as_uint(Bs[(n0 + g) * LDA + k0 + t]);
                uint32_t b1 = __float_as_uint(Bs[(n0 + g) * LDA + k0 + t + 4]);
                mma_tf32(c[0][nt], af[0], b0, b1);
                mma_tf32(c[1][nt], af[1], b0, b1);
            }
        }

        if (kt + 1 < 32) {
            float* Asn = gsm + ((kt + 1) & 1) * 2 * GEMM_BUF;
            float* Bsn = Asn + GEMM_BUF;
#pragma unroll
            for (int i = 0; i < 4; i++) {
                int row = lrow + 32 * i;
                Asn[row * LDA + lkq + 0] = f2tf32(stA[i].x);
                Asn[row * LDA + lkq + 1] = f2tf32(stA[i].y);
                Asn[row * LDA + lkq + 2] = f2tf32(stA[i].z);
                Asn[row * LDA + lkq + 3] = f2tf32(stA[i].w);
                Bsn[row * LDA + lkq + 0] = f2tf32(stB[i].x);
                Bsn[row * LDA + lkq + 1] = f2tf32(stB[i].y);
                Bsn[row * LDA + lkq + 2] = f2tf32(stB[i].z);
                Bsn[row * LDA + lkq + 3] = f2tf32(stB[i].w);
            }
            __syncthreads();
        }
    }

#pragma unroll
    for (int i = 0; i < 2; i++) {
        int m0 = mb + wm * 32 + i * 16;
        int r0 = m0 + g, r1 = m0 + g + 8;
#pragma unroll
        for (int nt = 0; nt < 8; nt++) {
            int ncg = nb + wn * 64 + nt * 8 + 2 * t;
            float c0 = c[i][nt][0], c1 = c[i][nt][1];
            float c2 = c[i][nt][2], c3 = c[i][nt][3];
            if (MODE == 0) {
                int w = ncg >> 10;
                int hn = ncg & 1023;
                int hh = hn >> 6, dd = hn & 63;
                float* dst = (w == 0) ? g_q : ((w == 1) ? g_k : g_v);
                if (w == 2) {   // V goes straight to flash: pre-convert to TF32
                    c0 = f2tf32(c0); c1 = f2tf32(c1);
                    c2 = f2tf32(c2); c3 = f2tf32(c3);
                }
                int bi0 = r0 >> 11, t0 = r0 & 2047;
                *(float2*)&dst[((size_t)(bi0 * NH + hh) * TT + t0) * DK + dd] =
                    make_float2(c0, c1);
                int bi1 = r1 >> 11, t1 = r1 & 2047;
                *(float2*)&dst[((size_t)(bi1 * NH + hh) * TT + t1) * DK + dd] =
                    make_float2(c2, c3);
            } else {
                *(float2*)&Cout[(size_t)r0 * DMODEL + ncg] = make_float2(c0, c1);
                *(float2*)&Cout[(size_t)r1 * DMODEL + ncg] = make_float2(c2, c3);
            }
        }
    }
}

// ---------------------------------------------------------------------------
// Flash attention, raw mma.sync m16n8k8 TF32, cp.async double-buffered K/V.
// CTA: 128 q-rows, 8 warps x 16 rows. K-tile 64. Q/O register-resident.
// Q,K,V arrive pre-converted to TF32 (Q also pre-scaled) — no CVT here.
// qt is processed in DESCENDING order for wave balance.
// ---------------------------------------------------------------------------
#define LDF 68
#define KV_TILE (64 * LDF)
#define FLASH_SMEM ((4 * KV_TILE + 8 * 16 * LDF) * 4)

__global__ void __launch_bounds__(256, 2) flash_mma_kernel() {
    extern __shared__ float fsm[];
    float* Kbuf[2] = { fsm,               fsm + 2 * KV_TILE };
    float* Vbuf[2] = { fsm + KV_TILE,     fsm + 3 * KV_TILE };
    float* Ps = fsm + 4 * KV_TILE;       // per warp [16][LDF]

    const int qt = (gridDim.x - 1) - blockIdx.x;   // big tiles first
    const int h  = blockIdx.y;
    const int bz = blockIdx.z;
    const int tid = threadIdx.x;
    const int w = tid >> 5;
    const int lane = tid & 31;
    const int g = lane >> 2;
    const int t = lane & 3;

    float* Pw = Ps + w * 16 * LDF;
    const size_t head_off = (size_t)(bz * NH + h) * TT * DK;
    const int rbase = qt * 128 + w * 16;

    const float* kbase = g_k + head_off;
    const float* vbase = g_v + head_off;

    // ---- Q fragments (already tf32 + pre-scaled) ----
    uint32_t qf[8][4];
    {
        const uint32_t* qp = (const uint32_t*)(g_q + head_off + (size_t)rbase * DK);
#pragma unroll
        for (int kc = 0; kc < 8; kc++) {
            qf[kc][0] = qp[(size_t)g * DK + 8 * kc + t];
            qf[kc][1] = qp[(size_t)(g + 8) * DK + 8 * kc + t];
            qf[kc][2] = qp[(size_t)g * DK + 8 * kc + t + 4];
            qf[kc][3] = qp[(size_t)(g + 8) * DK + 8 * kc + t + 4];
        }
    }

    float oa[8][4];
#pragma unroll
    for (int i = 0; i < 8; i++)
#pragma unroll
        for (int j = 0; j < 4; j++) oa[i][j] = 0.f;
    float m0 = -1e30f, m1 = -1e30f, l0 = 0.f, l1 = 0.f;

    const int ktiles = 2 * qt + 2;

    // prologue: prefetch tile 0
    {
        const float* kp = kbase;
        const float* vp = vbase;
#pragma unroll
        for (int i = 0; i < 4; i++) {
            int f4 = tid + 256 * i;
            int c = f4 >> 4, dq = (f4 & 15) << 2;
            uint32_t dk_ = (uint32_t)__cvta_generic_to_shared(&Kbuf[0][c * LDF + dq]);
            uint32_t dv_ = (uint32_t)__cvta_generic_to_shared(&Vbuf[0][c * LDF + dq]);
            CP_ASYNC16(dk_, kp + c * DK + dq);
            CP_ASYNC16(dv_, vp + c * DK + dq);
        }
        CP_COMMIT();
    }

    for (int j = 0; j < ktiles; j++) {
        CP_WAIT0();
        __syncthreads();     // tile j resident; all warps done with buffer (j+1)&1

        if (j + 1 < ktiles) {
            const float* kp = kbase + (size_t)(j + 1) * 64 * DK;
            const float* vp = vbase + (size_t)(j + 1) * 64 * DK;
            float* Kd = Kbuf[(j + 1) & 1];
            float* Vd = Vbuf[(j + 1) & 1];
#pragma unroll
            for (int i = 0; i < 4; i++) {
                int f4 = tid + 256 * i;
                int c = f4 >> 4, dq = (f4 & 15) << 2;
                uint32_t dk_ = (uint32_t)__cvta_generic_to_shared(&Kd[c * LDF + dq]);
                uint32_t dv_ = (uint32_t)__cvta_generic_to_shared(&Vd[c * LDF + dq]);
                CP_ASYNC16(dk_, kp + c * DK + dq);
                CP_ASYNC16(dv_, vp + c * DK + dq);
            }
            CP_COMMIT();
        }

        const float* Ks = Kbuf[j & 1];
        const float* Vs = Vbuf[j & 1];

        if (64 * j > rbase + 15) continue;   // warp fully above diagonal

        // ---- S = Q K^T ----
        float sa[8][4];
#pragma unroll
        for (int nt = 0; nt < 8; nt++) {
            sa[nt][0] = sa[nt][1] = sa[nt][2] = sa[nt][3] = 0.f;
#pragma unroll
            for (int kc = 0; kc < 8; kc++) {
                uint32_t b0 = __float_as_uint(Ks[(8 * nt + g) * LDF + 8 * kc + t]);
                uint32_t b1 = __float_as_uint(Ks[(8 * nt + g) * LDF + 8 * kc + t + 4]);
                mma_tf32(sa[nt], qf[kc], b0, b1);
            }
        }

        // ---- causal mask (diagonal region only) ----
        if (64 * j + 63 > rbase) {
            const int r0 = rbase + g, r1 = rbase + g + 8;
#pragma unroll
            for (int nt = 0; nt < 8; nt++) {
                int c0 = 64 * j + 8 * nt + 2 * t;
                if (c0 > r0)     sa[nt][0] = -1e30f;
                if (c0 + 1 > r0) sa[nt][1] = -1e30f;
                if (c0 > r1)     sa[nt][2] = -1e30f;
                if (c0 + 1 > r1) sa[nt][3] = -1e30f;
            }
        }

        // ---- online softmax (registers + quad shuffles) ----
        float mx0 = -1e30f, mx1 = -1e30f;
#pragma unroll
        for (int nt = 0; nt < 8; nt++) {
            mx0 = fmaxf(mx0, fmaxf(sa[nt][0], sa[nt][1]));
            mx1 = fmaxf(mx1, fmaxf(sa[nt][2], sa[nt][3]));
        }
        mx0 = fmaxf(mx0, __shfl_xor_sync(0xffffffffu, mx0, 1));
        mx0 = fmaxf(mx0, __shfl_xor_sync(0xffffffffu, mx0, 2));
        mx1 = fmaxf(mx1, __shfl_xor_sync(0xffffffffu, mx1, 1));
        mx1 = fmaxf(mx1, __shfl_xor_sync(0xffffffffu, mx1, 2));
        float mn0 = fmaxf(m0, mx0), mn1 = fmaxf(m1, mx1);
        float al0 = exp2f(m0 - mn0), al1 = exp2f(m1 - mn1);
        m0 = mn0; m1 = mn1;

        float sum0 = 0.f, sum1 = 0.f;
#pragma unroll
        for (int nt = 0; nt < 8; nt++) {
            float p0 = exp2f(sa[nt][0] - mn0);
            float p1 = exp2f(sa[nt][1] - mn0);
            float p2 = exp2f(sa[nt][2] - mn1);
            float p3 = exp2f(sa[nt][3] - mn1);
            sum0 += p0 + p1;
            sum1 += p2 + p3;
            Pw[g * LDF + 8 * nt + 2 * t]           = f2tf32(p0);
            Pw[g * LDF + 8 * nt + 2 * t + 1]       = f2tf32(p1);
            Pw[(g + 8) * LDF + 8 * nt + 2 * t]     = f2tf32(p2);
            Pw[(g + 8) * LDF + 8 * nt + 2 * t + 1] = f2tf32(p3);
        }
        sum0 += __shfl_xor_sync(0xffffffffu, sum0, 1);
        sum0 += __shfl_xor_sync(0xffffffffu, sum0, 2);
        sum1 += __shfl_xor_sync(0xffffffffu, sum1, 1);
        sum1 += __shfl_xor_sync(0xffffffffu, sum1, 2);
        l0 = l0 * al0 + sum0;
        l1 = l1 * al1 + sum1;

#pragma unroll
        for (int dt = 0; dt < 8; dt++) {
            oa[dt][0] *= al0; oa[dt][1] *= al0;
            oa[dt][2] *= al1; oa[dt][3] *= al1;
        }
        __syncwarp();

        // ---- O += P V ----
#pragma unroll
        for (int kc = 0; kc < 8; kc++) {
            uint32_t pf[4];
            pf[0] = __float_as_uint(Pw[g * LDF + 8 * kc + t]);
            pf[1] = __float_as_uint(Pw[(g + 8) * LDF + 8 * kc + t]);
            pf[2] = __float_as_uint(Pw[g * LDF + 8 * kc + t + 4]);
            pf[3] = __float_as_uint(Pw[(g + 8) * LDF + 8 * kc + t + 4]);
#pragma unroll
            for (int dt = 0; dt < 8; dt++) {
                uint32_t b0 = __float_as_uint(Vs[(8 * kc + t) * LDF + 8 * dt + g]);
                uint32_t b1 = __float_as_uint(Vs[(8 * kc + t + 4) * LDF + 8 * dt + g]);
                mma_tf32(oa[dt], pf, b0, b1);
            }
        }
        __syncwarp();
    }

    // ---- normalize & write [b*t][e] ----
    {
        float inv0 = 1.f / l0, inv1 = 1.f / l1;
        float* op0 = g_attn + (size_t)(bz * TT + rbase + g) * DMODEL + h * DK;
        float* op1 = g_attn + (size_t)(bz * TT + rbase + g + 8) * DMODEL + h * DK;
#pragma unroll
        for (int dt = 0; dt < 8; dt++) {
            *(float2*)&op0[8 * dt + 2 * t] = make_float2(oa[dt][0] * inv0, oa[dt][1] * inv0);
            *(float2*)&op1[8 * dt + 2 * t] = make_float2(oa[dt][2] * inv1, oa[dt][3] * inv1);
        }
    }
}

// ---------------------------------------------------------------------------
extern "C" void kernel_launch(void* const* d_in, const int* in_sizes, int n_in,
                              void* d_out, int out_size) {
    (void)in_sizes; (void)n_in; (void)out_size;
    const float* x  = (const float*)d_in[0];
    const float* Wq = (const float*)d_in[2];
    const float* Wk = (const float*)d_in[3];
    const float* Wv = (const float*)d_in[4];
    const float* Wo = (const float*)d_in[5];
    float* out = (float*)d_out;

    cudaFuncSetAttribute(flash_mma_kernel,
                         cudaFuncAttributeMaxDynamicSharedMemorySize, FLASH_SMEM);
    cudaFuncSetAttribute(gemm_mma_kernel<0>,
                         cudaFuncAttributeMaxDynamicSharedMemorySize, GEMM_SMEM);
    cudaFuncSetAttribute(gemm_mma_kernel<1>,
                         cudaFuncAttributeMaxDynamicSharedMemorySize, GEMM_SMEM);

    rope_table_kernel<<<(TT * 32 + 255) / 256, 256>>>();

    gemm_mma_kernel<0><<<dim3(MROWS / 128, 3072 / 128), 256, GEMM_SMEM>>>(
        x, Wq, Wk, Wv, nullptr);

    rope_apply_kernel<<<(2 * BB * NH * TT * 32 + 255) / 256, 256>>>();

    flash_mma_kernel<<<dim3(TT / 128, NH, BB), 256, FLASH_SMEM>>>();

    gemm_mma_kernel<1><<<dim3(MROWS / 128, DMODEL / 128), 256, GEMM_SMEM>>>(
        nullptr, Wo, nullptr, nullptr, out);
}

// round 8
// speedup vs baseline: 1.0643x; 1.0643x over previous
#include <cuda_runtime.h>
#include <math.h>
#include <stdint.h>

#define BB 2
#define TT 2048
#define DMODEL 1024
#define NH 16
#define DK 64
#define MROWS (BB * TT)   // 4096

// ---- scratch (static device memory; no allocations allowed) ----
__device__ float g_q[(size_t)BB * NH * TT * DK];
__device__ float g_k[(size_t)BB * NH * TT * DK];
__device__ float g_v[(size_t)BB * NH * TT * DK];
__device__ float g_attn[(size_t)MROWS * DMODEL];
__device__ float g_cos[TT * 32];
__device__ float g_sin[TT * 32];

// ---------------------------------------------------------------------------
__device__ __forceinline__ float f2tf32(float x) {
    float y;
    asm("cvt.rna.tf32.f32 %0, %1;" : "=f"(y) : "f"(x));
    return y;
}

__device__ __forceinline__ void mma_tf32(float c[4],
                                         const uint32_t a[4],
                                         uint32_t b0, uint32_t b1) {
    asm volatile(
        "mma.sync.aligned.m16n8k8.row.col.f32.tf32.tf32.f32 "
        "{%0,%1,%2,%3}, {%4,%5,%6,%7}, {%8,%9}, {%0,%1,%2,%3};"
        : "+f"(c[0]), "+f"(c[1]), "+f"(c[2]), "+f"(c[3])
        : "r"(a[0]), "r"(a[1]), "r"(a[2]), "r"(a[3]), "r"(b0), "r"(b1));
}

// ---------------------------------------------------------------------------
// RoPE tables + apply. rope_apply:
//   - pre-scales Q by 0.125*log2(e) (softmax uses exp2)
//   - converts Q and K to TF32 (flash consumes raw bits, no CVT there)
// ---------------------------------------------------------------------------
__global__ void rope_table_kernel() {
    int i = blockIdx.x * blockDim.x + threadIdx.x;
    if (i >= TT * 32) return;
    int t = i >> 5, j = i & 31;
    double inv = pow(10000.0, -((double)(2 * j)) / 64.0);
    float angf = (float)t * (float)inv;
    g_cos[i] = (float)cos((double)angf);
    g_sin[i] = (float)sin((double)angf);
}

__global__ void rope_apply_kernel() {
    int i = blockIdx.x * blockDim.x + threadIdx.x;
    const int per = BB * NH * TT * 32;
    if (i >= 2 * per) return;
    const bool isq = (i < per);
    float* arr = isq ? g_q : g_k;
    const float sc = isq ? (0.125f * 1.4426950408889634f) : 1.0f;
    int p = i & (per - 1);
    int j = p & 31;
    int bht = p >> 5;
    int t = bht & (TT - 1);
    float c = g_cos[t * 32 + j];
    float s = g_sin[t * 32 + j];
    size_t base = (size_t)bht * DK + 2 * j;
    float x1 = arr[base], x2 = arr[base + 1];
    arr[base]     = f2tf32((c * x1 - s * x2) * sc);
    arr[base + 1] = f2tf32((s * x1 + c * x2) * sc);
}

// ---------------------------------------------------------------------------
// TF32 raw-mma SGEMM, software-pipelined (register staging + double smem buf).
// MODE 0: A=x, W={Wq,Wk,Wv}, scatter into g_q/g_k/g_v [b][h][t][d];
//         V segment converted to TF32 at the epilogue (flash reads raw bits).
// MODE 1: A=g_attn, W=Wo, C=out row-major
// ---------------------------------------------------------------------------
#define LDA 36
#define GEMM_BUF (128 * LDA)
#define GEMM_SMEM (4 * GEMM_BUF * 4)

template <int MODE>
__global__ void __launch_bounds__(256, 2) gemm_mma_kernel(
    const float* __restrict__ A_,
    const float* __restrict__ W0,
    const float* __restrict__ W1,
    const float* __restrict__ W2,
    float* __restrict__ Cout)
{
    extern __shared__ float gsm[];

    const int tid = threadIdx.x;
    const int warp = tid >> 5;
    const int lane = tid & 31;
    const int g = lane >> 2;
    const int t = lane & 3;
    const int wm = warp >> 1;
    const int wn = warp & 1;
    const int mb = blockIdx.x * 128;
    const int nb = blockIdx.y * 128;

    const float* Ap = (MODE == 0) ? A_ : g_attn;
    const float* Wp;
    int nloc;
    if (MODE == 0) {
        int w = nb >> 10;
        Wp = (w == 0) ? W0 : ((w == 1) ? W1 : W2);
        nloc = nb & 1023;
    } else {
        Wp = W0;
        nloc = nb;
    }

    const int lrow = tid >> 3;
    const int lkq  = (tid & 7) << 2;

    float4 stA[4], stB[4];

#pragma unroll
    for (int i = 0; i < 4; i++) {
        int row = lrow + 32 * i;
        stA[i] = *(const float4*)(Ap + (size_t)(mb + row) * 1024 + lkq);
        stB[i] = *(const float4*)(Wp + (size_t)(nloc + row) * 1024 + lkq);
    }
    {
        float* As = gsm;
        float* Bs = gsm + GEMM_BUF;
#pragma unroll
        for (int i = 0; i < 4; i++) {
            int row = lrow + 32 * i;
            As[row * LDA + lkq + 0] = f2tf32(stA[i].x);
            As[row * LDA + lkq + 1] = f2tf32(stA[i].y);
            As[row * LDA + lkq + 2] = f2tf32(stA[i].z);
            As[row * LDA + lkq + 3] = f2tf32(stA[i].w);
            Bs[row * LDA + lkq + 0] = f2tf32(stB[i].x);
            Bs[row * LDA + lkq + 1] = f2tf32(stB[i].y);
            Bs[row * LDA + lkq + 2] = f2tf32(stB[i].z);
            Bs[row * LDA + lkq + 3] = f2tf32(stB[i].w);
        }
    }
    __syncthreads();

    float c[2][8][4];
#pragma unroll
    for (int i = 0; i < 2; i++)
#pragma unroll
        for (int nt = 0; nt < 8; nt++)
#pragma unroll
            for (int e = 0; e < 4; e++) c[i][nt][e] = 0.f;

    for (int kt = 0; kt < 32; kt++) {
        if (kt + 1 < 32) {
            int kb = (kt + 1) * 32;
#pragma unroll
            for (int i = 0; i < 4; i++) {
                int row = lrow + 32 * i;
                stA[i] = *(const float4*)(Ap + (size_t)(mb + row) * 1024 + kb + lkq);
                stB[i] = *(const float4*)(Wp + (size_t)(nloc + row) * 1024 + kb + lkq);
            }
        }

        const float* As = gsm + (kt & 1) * 2 * GEMM_BUF;
        const float* Bs = As + GEMM_BUF;

#pragma unroll
        for (int k0 = 0; k0 < 32; k0 += 8) {
            uint32_t af[2][4];
#pragma unroll
            for (int i = 0; i < 2; i++) {
                int m0 = wm * 32 + i * 16;
                af[i][0] = __float_as_uint(As[(m0 + g) * LDA + k0 + t]);
                af[i][1] = __float_as_uint(As[(m0 + g + 8) * LDA + k0 + t]);
                af[i][2] = __float_as_uint(As[(m0 + g) * LDA + k0 + t + 4]);
                af[i][3] = __float_as_uint(As[(m0 + g + 8) * LDA + k0 + t + 4]);
            }
#pragma unroll
            for (int nt = 0; nt < 8; nt++) {
                int n0 = wn * 64 + nt * 8;
                uint32_t b0 = __float_as_uint(Bs[(n0 + g) * LDA + k0 + t]);
                uint32_t b1 = __float_as_uint(Bs[(n0 + g) * LDA + k0 + t + 4]);
                mma_tf32(c[0][nt], af[0], b0, b1);
                mma_tf32(c[1][nt], af[1], b0, b1);
            }
        }

        if (kt + 1 < 32) {
            float* Asn = gsm + ((kt + 1) & 1) * 2 * GEMM_BUF;
            float* Bsn = Asn + GEMM_BUF;
#pragma unroll
            for (int i = 0; i < 4; i++) {
                int row = lrow + 32 * i;
                Asn[row * LDA + lkq + 0] = f2tf32(stA[i].x);
                Asn[row * LDA + lkq + 1] = f2tf32(stA[i].y);
                Asn[row * LDA + lkq + 2] = f2tf32(stA[i].z);
                Asn[row * LDA + lkq + 3] = f2tf32(stA[i].w);
                Bsn[row * LDA + lkq + 0] = f2tf32(stB[i].x);
                Bsn[row * LDA + lkq + 1] = f2tf32(stB[i].y);
                Bsn[row * LDA + lkq + 2] = f2tf32(stB[i].z);
                Bsn[row * LDA + lkq + 3] = f2tf32(stB[i].w);
            }
            __syncthreads();
        }
    }

#pragma unroll
    for (int i = 0; i < 2; i++) {
        int m0 = mb + wm * 32 + i * 16;
        int r0 = m0 + g, r1 = m0 + g + 8;
#pragma unroll
        for (int nt = 0; nt < 8; nt++) {
            int ncg = nb + wn * 64 + nt * 8 + 2 * t;
            float c0 = c[i][nt][0], c1 = c[i][nt][1];
            float c2 = c[i][nt][2], c3 = c[i][nt][3];
            if (MODE == 0) {
                int w = ncg >> 10;
                int hn = ncg & 1023;
                int hh = hn >> 6, dd = hn & 63;
                float* dst = (w == 0) ? g_q : ((w == 1) ? g_k : g_v);
                if (w == 2) {   // V goes straight to flash: pre-convert to TF32
                    c0 = f2tf32(c0); c1 = f2tf32(c1);
                    c2 = f2tf32(c2); c3 = f2tf32(c3);
                }
                int bi0 = r0 >> 11, t0 = r0 & 2047;
                *(float2*)&dst[((size_t)(bi0 * NH + hh) * TT + t0) * DK + dd] =
                    make_float2(c0, c1);
                int bi1 = r1 >> 11, t1 = r1 & 2047;
                *(float2*)&dst[((size_t)(bi1 * NH + hh) * TT + t1) * DK + dd] =
                    make_float2(c2, c3);
            } else {
                *(float2*)&Cout[(size_t)r0 * DMODEL + ncg] = make_float2(c0, c1);
                *(float2*)&Cout[(size_t)r1 * DMODEL + ncg] = make_float2(c2, c3);
            }
        }
    }
}

// ---------------------------------------------------------------------------
// Flash attention, raw mma.sync m16n8k8 TF32.  R6 structure restored:
// synchronous LDG->STS (L1-cached; co-resident CTAs share K/V of same head),
// 2 barriers per k-tile, forward qt order.
// Inputs arrive pre-converted to TF32 (Q also pre-scaled) — zero CVTs here.
// ---------------------------------------------------------------------------
#define LDF 68
#define FLASH_SMEM ((2 * 64 * LDF + 8 * 16 * LDF) * 4)

__global__ void __launch_bounds__(256, 2) flash_mma_kernel() {
    extern __shared__ float fsm[];
    float* Ks = fsm;                     // [64][LDF]  rows = k-seq c, cols = d
    float* Vs = fsm + 64 * LDF;          // [64][LDF]
    float* Ps = fsm + 2 * 64 * LDF;      // per warp [16][LDF]

    const int qt = blockIdx.x;
    const int h  = blockIdx.y;
    const int bz = blockIdx.z;
    const int tid = threadIdx.x;
    const int w = tid >> 5;
    const int lane = tid & 31;
    const int g = lane >> 2;
    const int t = lane & 3;

    float* Pw = Ps + w * 16 * LDF;
    const size_t head_off = (size_t)(bz * NH + h) * TT * DK;
    const int rbase = qt * 128 + w * 16;

    // ---- Q fragments (already tf32 + pre-scaled) ----
    uint32_t qf[8][4];
    {
        const uint32_t* qp = (const uint32_t*)(g_q + head_off + (size_t)rbase * DK);
#pragma unroll
        for (int kc = 0; kc < 8; kc++) {
            qf[kc][0] = qp[(size_t)g * DK + 8 * kc + t];
            qf[kc][1] = qp[(size_t)(g + 8) * DK + 8 * kc + t];
            qf[kc][2] = qp[(size_t)g * DK + 8 * kc + t + 4];
            qf[kc][3] = qp[(size_t)(g + 8) * DK + 8 * kc + t + 4];
        }
    }

    float oa[8][4];
#pragma unroll
    for (int i = 0; i < 8; i++)
#pragma unroll
        for (int j = 0; j < 4; j++) oa[i][j] = 0.f;
    float m0 = -1e30f, m1 = -1e30f, l0 = 0.f, l1 = 0.f;

    const int ktiles = 2 * qt + 2;
    for (int j = 0; j < ktiles; j++) {
        __syncthreads();                 // all consumers of previous tile done
        {
            const float* kp = g_k + head_off + (size_t)j * 64 * DK;
            const float* vp = g_v + head_off + (size_t)j * 64 * DK;
#pragma unroll
            for (int i = 0; i < 4; i++) {
                int f4 = tid + 256 * i;
                int c = f4 >> 4, dq = (f4 & 15) << 2;
                *(float4*)&Ks[c * LDF + dq] = *(const float4*)(kp + c * DK + dq);
                *(float4*)&Vs[c * LDF + dq] = *(const float4*)(vp + c * DK + dq);
            }
        }
        __syncthreads();

        if (64 * j > rbase + 15) continue;   // warp fully above diagonal

        // ---- S = Q K^T ----
        float sa[8][4];
#pragma unroll
        for (int nt = 0; nt < 8; nt++) {
            sa[nt][0] = sa[nt][1] = sa[nt][2] = sa[nt][3] = 0.f;
#pragma unroll
            for (int kc = 0; kc < 8; kc++) {
                uint32_t b0 = __float_as_uint(Ks[(8 * nt + g) * LDF + 8 * kc + t]);
                uint32_t b1 = __float_as_uint(Ks[(8 * nt + g) * LDF + 8 * kc + t + 4]);
                mma_tf32(sa[nt], qf[kc], b0, b1);
            }
        }

        // ---- causal mask (diagonal region only) ----
        if (64 * j + 63 > rbase) {
            const int r0 = rbase + g, r1 = rbase + g + 8;
#pragma unroll
            for (int nt = 0; nt < 8; nt++) {
                int c0 = 64 * j + 8 * nt + 2 * t;
                if (c0 > r0)     sa[nt][0] = -1e30f;
                if (c0 + 1 > r0) sa[nt][1] = -1e30f;
                if (c0 > r1)     sa[nt][2] = -1e30f;
                if (c0 + 1 > r1) sa[nt][3] = -1e30f;
            }
        }

        // ---- online softmax (registers + quad shuffles) ----
        float mx0 = -1e30f, mx1 = -1e30f;
#pragma unroll
        for (int nt = 0; nt < 8; nt++) {
            mx0 = fmaxf(mx0, fmaxf(sa[nt][0], sa[nt][1]));
            mx1 = fmaxf(mx1, fmaxf(sa[nt][2], sa[nt][3]));
        }
        mx0 = fmaxf(mx0, __shfl_xor_sync(0xffffffffu, mx0, 1));
        mx0 = fmaxf(mx0, __shfl_xor_sync(0xffffffffu, mx0, 2));
        mx1 = fmaxf(mx1, __shfl_xor_sync(0xffffffffu, mx1, 1));
        mx1 = fmaxf(mx1, __shfl_xor_sync(0xffffffffu, mx1, 2));
        float mn0 = fmaxf(m0, mx0), mn1 = fmaxf(m1, mx1);
        float al0 = exp2f(m0 - mn0), al1 = exp2f(m1 - mn1);
        m0 = mn0; m1 = mn1;

        float sum0 = 0.f, sum1 = 0.f;
#pragma unroll
        for (int nt = 0; nt < 8; nt++) {
            float p0 = exp2f(sa[nt][0] - mn0);
            float p1 = exp2f(sa[nt][1] - mn0);
            float p2 = exp2f(sa[nt][2] - mn1);
            float p3 = exp2f(sa[nt][3] - mn1);
            sum0 += p0 + p1;
            sum1 += p2 + p3;
            Pw[g * LDF + 8 * nt + 2 * t]           = f2tf32(p0);
            Pw[g * LDF + 8 * nt + 2 * t + 1]       = f2tf32(p1);
            Pw[(g + 8) * LDF + 8 * nt + 2 * t]     = f2tf32(p2);
            Pw[(g + 8) * LDF + 8 * nt + 2 * t + 1] = f2tf32(p3);
        }
        sum0 += __shfl_xor_sync(0xffffffffu, sum0, 1);
        sum0 += __shfl_xor_sync(0xffffffffu, sum0, 2);
        sum1 += __shfl_xor_sync(0xffffffffu, sum1, 1);
        sum1 += __shfl_xor_sync(0xffffffffu, sum1, 2);
        l0 = l0 * al0 + sum0;
        l1 = l1 * al1 + sum1;

#pragma unroll
        for (int dt = 0; dt < 8; dt++) {
            oa[dt][0] *= al0; oa[dt][1] *= al0;
            oa[dt][2] *= al1; oa[dt][3] *= al1;
        }
        __syncwarp();

        // ---- O += P V ----
#pragma unroll
        for (int kc = 0; kc < 8; kc++) {
            uint32_t pf[4];
            pf[0] = __float_as_uint(Pw[g * LDF + 8 * kc + t]);
            pf[1] = __float_as_uint(Pw[(g + 8) * LDF + 8 * kc + t]);
            pf[2] = __float_as_uint(Pw[g * LDF + 8 * kc + t + 4]);
            pf[3] = __float_as_uint(Pw[(g + 8) * LDF + 8 * kc + t + 4]);
#pragma unroll
            for (int dt = 0; dt < 8; dt++) {
                uint32_t b0 = __float_as_uint(Vs[(8 * kc + t) * LDF + 8 * dt + g]);
                uint32_t b1 = __float_as_uint(Vs[(8 * kc + t + 4) * LDF + 8 * dt + g]);
                mma_tf32(oa[dt], pf, b0, b1);
            }
        }
        __syncwarp();
    }

    // ---- normalize & write [b*t][e] ----
    {
        float inv0 = 1.f / l0, inv1 = 1.f / l1;
        float* op0 = g_attn + (size_t)(bz * TT + rbase + g) * DMODEL + h * DK;
        float* op1 = g_attn + (size_t)(bz * TT + rbase + g + 8) * DMODEL + h * DK;
#pragma unroll
        for (int dt = 0; dt < 8; dt++) {
            *(float2*)&op0[8 * dt + 2 * t] = make_float2(oa[dt][0] * inv0, oa[dt][1] * inv0);
            *(float2*)&op1[8 * dt + 2 * t] = make_float2(oa[dt][2] * inv1, oa[dt][3] * inv1);
        }
    }
}

// ---------------------------------------------------------------------------
extern "C" void kernel_launch(void* const* d_in, const int* in_sizes, int n_in,
                              void* d_out, int out_size) {
    (void)in_sizes; (void)n_in; (void)out_size;
    const float* x  = (const float*)d_in[0];
    const float* Wq = (const float*)d_in[2];
    const float* Wk = (const float*)d_in[3];
    const float* Wv = (const float*)d_in[4];
    const float* Wo = (const float*)d_in[5];
    float* out = (float*)d_out;

    cudaFuncSetAttribute(flash_mma_kernel,
                         cudaFuncAttributeMaxDynamicSharedMemorySize, FLASH_SMEM);
    cudaFuncSetAttribute(gemm_mma_kernel<0>,
                         cudaFuncAttributeMaxDynamicSharedMemorySize, GEMM_SMEM);
    cudaFuncSetAttribute(gemm_mma_kernel<1>,
                         cudaFuncAttributeMaxDynamicSharedMemorySize, GEMM_SMEM);

    rope_table_kernel<<<(TT * 32 + 255) / 256, 256>>>();

    gemm_mma_kernel<0><<<dim3(MROWS / 128, 3072 / 128), 256, GEMM_SMEM>>>(
        x, Wq, Wk, Wv, nullptr);

    rope_apply_kernel<<<(2 * BB * NH * TT * 32 + 255) / 256, 256>>>();

    flash_mma_kernel<<<dim3(TT / 128, NH, BB), 256, FLASH_SMEM>>>();

    gemm_mma_kernel<1><<<dim3(MROWS / 128, DMODEL / 128), 256, GEMM_SMEM>>>(
        nullptr, Wo, nullptr, nullptr, out);
}

// round 10
// speedup vs baseline: 1.8543x; 1.7424x over previous
#include <cuda_runtime.h>
#include <cuda_fp16.h>
#include <math.h>
#include <stdint.h>

#define BB 2
#define TT 2048
#define DMODEL 1024
#define NH 16
#define DK 64
#define MROWS (BB * TT)   // 4096

// ---- scratch (static device memory; no allocations allowed) ----
__device__ __half g_qh[(size_t)BB * NH * TT * DK];   // [b][h][t][d] fp16
__device__ __half g_kh[(size_t)BB * NH * TT * DK];   // [b][h][t][d] fp16
__device__ __half g_vh[(size_t)BB * NH * DK * TT];   // [b][h][d][t] fp16 (transposed)
__device__ float  g_attn[(size_t)MROWS * DMODEL];
__device__ float  g_cos[TT * 32];
__device__ float  g_sin[TT * 32];

// ---------------------------------------------------------------------------
__device__ __forceinline__ uint32_t pack_h2(float a, float b) {
    __half2 h = __floats2half2_rn(a, b);
    return *reinterpret_cast<uint32_t*>(&h);
}

// m16n8k16 f16 with f32 accumulate.
// A(16x16): a0=(g,2t:2t+1) a1=(g+8,2t:2t+1) a2=(g,8+2t:+1) a3=(g+8,8+2t:+1)
// B(16x8) col-major: b0=(k=2t:2t+1, n=g)  b1=(k=8+2t:+1, n=g)
// C(16x8): c0=(g,2t) c1=(g,2t+1) c2=(g+8,2t) c3=(g+8,2t+1)
__device__ __forceinline__ void mma_f16(float c[4],
                                        const uint32_t a[4],
                                        uint32_t b0, uint32_t b1) {
    asm volatile(
        "mma.sync.aligned.m16n8k16.row.col.f32.f16.f16.f32 "
        "{%0,%1,%2,%3}, {%4,%5,%6,%7}, {%8,%9}, {%0,%1,%2,%3};"
        : "+f"(c[0]), "+f"(c[1]), "+f"(c[2]), "+f"(c[3])
        : "r"(a[0]), "r"(a[1]), "r"(a[2]), "r"(a[3]), "r"(b0), "r"(b1));
}

// ---------------------------------------------------------------------------
// RoPE tables + apply (on fp16 q/k, fp32 math in between; Q pre-scaled).
// ---------------------------------------------------------------------------
__global__ void rope_table_kernel() {
    int i = blockIdx.x * blockDim.x + threadIdx.x;
    if (i >= TT * 32) return;
    int t = i >> 5, j = i & 31;
    double inv = pow(10000.0, -((double)(2 * j)) / 64.0);
    float angf = (float)t * (float)inv;
    g_cos[i] = (float)cos((double)angf);
    g_sin[i] = (float)sin((double)angf);
}

__global__ void rope_apply_kernel() {
    int i = blockIdx.x * blockDim.x + threadIdx.x;
    const int per = BB * NH * TT * 32;
    if (i >= 2 * per) return;
    const bool isq = (i < per);
    __half2* arr = (__half2*)(isq ? g_qh : g_kh);
    const float sc = isq ? (0.125f * 1.4426950408889634f) : 1.0f;
    int p = i & (per - 1);
    int j = p & 31;
    int bht = p >> 5;
    int t = bht & (TT - 1);
    float c = g_cos[t * 32 + j];
    float s = g_sin[t * 32 + j];
    size_t idx = (size_t)bht * 32 + j;
    float2 x = __half22float2(arr[idx]);
    arr[idx] = __floats2half2_rn((c * x.x - s * x.y) * sc,
                                 (s * x.x + c * x.y) * sc);
}

// ---------------------------------------------------------------------------
// FP16 raw-mma GEMM, software-pipelined (register staging + double smem buf).
// C[m,n] = sum_k A[m,k]*W[n,k] (NT). Block 128x128, k-tile 32, 8 warps,
// warp tile 32(M)x64(N) = 2 m-frags x 8 n-frags of m16n8k16 (2 k0 steps).
// smem tiles stored as fp16 (converted at fill), ld = 40 halfs.
// MODE 0: A=x, W={Wq,Wk,Wv}; q/k -> g_qh/g_kh [b][h][t][d] fp16;
//         v -> g_vh [b][h][d][t] fp16 (transposed).
// MODE 1: A=g_attn, W=Wo, C=out fp32 row-major.
// ---------------------------------------------------------------------------
#define LDH 40                    // smem leading dim in halfs
#define GBUF_H (128 * LDH)        // halfs per A (or B) buffer
#define GEMM_SMEM (4 * GBUF_H * 2)

template <int MODE>
__global__ void __launch_bounds__(256, 2) gemm_mma_kernel(
    const float* __restrict__ A_,
    const float* __restrict__ W0,
    const float* __restrict__ W1,
    const float* __restrict__ W2,
    float* __restrict__ Cout)
{
    extern __shared__ __half gsmh[];

    const int tid = threadIdx.x;
    const int warp = tid >> 5;
    const int lane = tid & 31;
    const int g = lane >> 2;
    const int t = lane & 3;
    const int wm = warp >> 1;
    const int wn = warp & 1;
    const int mb = blockIdx.x * 128;
    const int nb = blockIdx.y * 128;

    const float* Ap = (MODE == 0) ? A_ : g_attn;
    const float* Wp;
    int nloc;
    if (MODE == 0) {
        int w = nb >> 10;
        Wp = (w == 0) ? W0 : ((w == 1) ? W1 : W2);
        nloc = nb & 1023;
    } else {
        Wp = W0;
        nloc = nb;
    }

    const int lrow = tid >> 3;          // base row, step 32
    const int lkq  = (tid & 7) << 2;    // k offset (4 elements)

    float4 stA[4], stB[4];

#pragma unroll
    for (int i = 0; i < 4; i++) {
        int row = lrow + 32 * i;
        stA[i] = *(const float4*)(Ap + (size_t)(mb + row) * 1024 + lkq);
        stB[i] = *(const float4*)(Wp + (size_t)(nloc + row) * 1024 + lkq);
    }
    {
        __half* As = gsmh;
        __half* Bs = gsmh + GBUF_H;
#pragma unroll
        for (int i = 0; i < 4; i++) {
            int row = lrow + 32 * i;
            *(uint2*)&As[row * LDH + lkq] =
                make_uint2(pack_h2(stA[i].x, stA[i].y), pack_h2(stA[i].z, stA[i].w));
            *(uint2*)&Bs[row * LDH + lkq] =
                make_uint2(pack_h2(stB[i].x, stB[i].y), pack_h2(stB[i].z, stB[i].w));
        }
    }
    __syncthreads();

    float c[2][8][4];
#pragma unroll
    for (int i = 0; i < 2; i++)
#pragma unroll
        for (int nt = 0; nt < 8; nt++)
#pragma unroll
            for (int e = 0; e < 4; e++) c[i][nt][e] = 0.f;

    for (int kt = 0; kt < 32; kt++) {
        if (kt + 1 < 32) {
            int kb = (kt + 1) * 32;
#pragma unroll
            for (int i = 0; i < 4; i++) {
                int row = lrow + 32 * i;
                stA[i] = *(const float4*)(Ap + (size_t)(mb + row) * 1024 + kb + lkq);
                stB[i] = *(const float4*)(Wp + (size_t)(nloc + row) * 1024 + kb + lkq);
            }
        }

        const uint32_t* As_u = (const uint32_t*)(gsmh + (kt & 1) * 2 * GBUF_H);
        const uint32_t* Bs_u = As_u + GBUF_H / 2;

#pragma unroll
        for (int k0 = 0; k0 < 2; k0++) {            // k0h = 0, 8 (uint units)
            const int k0h = k0 * 8;
            uint32_t af[2][4];
#pragma unroll
            for (int i = 0; i < 2; i++) {
                int m0 = wm * 32 + i * 16;
                af[i][0] = As_u[(m0 + g)     * (LDH / 2) + k0h + t];
                af[i][1] = As_u[(m0 + g + 8) * (LDH / 2) + k0h + t];
                af[i][2] = As_u[(m0 + g)     * (LDH / 2) + k0h + 4 + t];
                af[i][3] = As_u[(m0 + g + 8) * (LDH / 2) + k0h + 4 + t];
            }
#pragma unroll
            for (int nt = 0; nt < 8; nt++) {
                int n0 = wn * 64 + nt * 8;
                uint32_t b0 = Bs_u[(n0 + g) * (LDH / 2) + k0h + t];
                uint32_t b1 = Bs_u[(n0 + g) * (LDH / 2) + k0h + 4 + t];
                mma_f16(c[0][nt], af[0], b0, b1);
                mma_f16(c[1][nt], af[1], b0, b1);
            }
        }

        if (kt + 1 < 32) {
            __half* Asn = gsmh + ((kt + 1) & 1) * 2 * GBUF_H;
            __half* Bsn = Asn + GBUF_H;
#pragma unroll
            for (int i = 0; i < 4; i++) {
                int row = lrow + 32 * i;
                *(uint2*)&Asn[row * LDH + lkq] =
                    make_uint2(pack_h2(stA[i].x, stA[i].y), pack_h2(stA[i].z, stA[i].w));
                *(uint2*)&Bsn[row * LDH + lkq] =
                    make_uint2(pack_h2(stB[i].x, stB[i].y), pack_h2(stB[i].z, stB[i].w));
            }
            __syncthreads();
        }
    }

    // ---- epilogue ----
#pragma unroll
    for (int i = 0; i < 2; i++) {
        int m0 = mb + wm * 32 + i * 16;
        int r0 = m0 + g, r1 = m0 + g + 8;
#pragma unroll
        for (int nt = 0; nt < 8; nt++) {
            int ncg = nb + wn * 64 + nt * 8 + 2 * t;
            float c0 = c[i][nt][0], c1 = c[i][nt][1];
            float c2 = c[i][nt][2], c3 = c[i][nt][3];
            if (MODE == 0) {
                int w = ncg >> 10;
                int hn = ncg & 1023;
                int hh = hn >> 6, dd = hn & 63;
                int bi0 = r0 >> 11, t0 = r0 & 2047;
                int bi1 = r1 >> 11, t1 = r1 & 2047;
                if (w < 2) {
                    __half* dst = (w == 0) ? g_qh : g_kh;
                    *(__half2*)&dst[((size_t)(bi0 * NH + hh) * TT + t0) * DK + dd] =
                        __floats2half2_rn(c0, c1);
                    *(__half2*)&dst[((size_t)(bi1 * NH + hh) * TT + t1) * DK + dd] =
                        __floats2half2_rn(c2, c3);
                } else {
                    // V transposed: [b][h][d][t]
                    size_t b0i = ((size_t)(bi0 * NH + hh) * DK + dd) * TT + t0;
                    g_vh[b0i]      = __float2half_rn(c0);
                    g_vh[b0i + TT] = __float2half_rn(c1);
                    size_t b1i = ((size_t)(bi1 * NH + hh) * DK + dd) * TT + t1;
                    g_vh[b1i]      = __float2half_rn(c2);
                    g_vh[b1i + TT] = __float2half_rn(c3);
                }
            } else {
                *(float2*)&Cout[(size_t)r0 * DMODEL + ncg] = make_float2(c0, c1);
                *(float2*)&Cout[(size_t)r1 * DMODEL + ncg] = make_float2(c2, c3);
            }
        }
    }
}

// ---------------------------------------------------------------------------
// Flash attention, fp16 m16n8k16.  R6/R8 structure (sync LDG->STS, L1-cached,
// 2 barriers/iter, forward qt).  Q/O register-resident; P packed to half2 in
// registers (A-frag == C-frag rows/cols) — NO P smem at all.
// smem: Ks[64][72] halfs ([c][d]), Vt[64][72] halfs ([d][c]).
// Fill uses uint4 chunks: 512 chunks x 8 halfs = 2 tiles of 64x64.
// ---------------------------------------------------------------------------
#define LDKH 72
#define FLASH_SMEM (2 * 64 * LDKH * 2)

__global__ void __launch_bounds__(256, 2) flash_mma_kernel() {
    extern __shared__ __half fsh[];
    __half* Ks = fsh;                   // [c][d]
    __half* Vt = fsh + 64 * LDKH;       // [d][c]

    const int qt = blockIdx.x;
    const int h  = blockIdx.y;
    const int bz = blockIdx.z;
    const int tid = threadIdx.x;
    const int lane = tid & 31;
    const int w = tid >> 5;
    const int g = lane >> 2;
    const int t = lane & 3;

    const size_t head_off = (size_t)(bz * NH + h) * TT * DK;
    const int rbase = qt * 128 + w * 16;

    const __half* kbase = g_kh + head_off;
    const __half* vbase = g_vh + (size_t)(bz * NH + h) * DK * TT;

    // ---- Q fragments (fp16, pre-scaled by rope) ----
    uint32_t qf[4][4];
    {
        const __half* qp = g_qh + head_off + (size_t)rbase * DK;
#pragma unroll
        for (int kc = 0; kc < 4; kc++) {
            qf[kc][0] = *(const uint32_t*)&qp[(size_t)g * DK + 16 * kc + 2 * t];
            qf[kc][1] = *(const uint32_t*)&qp[(size_t)(g + 8) * DK + 16 * kc + 2 * t];
            qf[kc][2] = *(const uint32_t*)&qp[(size_t)g * DK + 16 * kc + 8 + 2 * t];
            qf[kc][3] = *(const uint32_t*)&qp[(size_t)(g + 8) * DK + 16 * kc + 8 + 2 * t];
        }
    }

    float oa[8][4];
#pragma unroll
    for (int i = 0; i < 8; i++)
#pragma unroll
        for (int j = 0; j < 4; j++) oa[i][j] = 0.f;
    float m0 = -1e30f, m1 = -1e30f, l0 = 0.f, l1 = 0.f;

    const int ktiles = 2 * qt + 2;
    for (int j = 0; j < ktiles; j++) {
        __syncthreads();                 // all consumers of previous tile done
        {
            const __half* kp = kbase + (size_t)j * 64 * DK;
            const __half* vp = vbase + 64 * j;
#pragma unroll
            for (int i = 0; i < 2; i++) {
                int f8 = tid + 256 * i;          // 8-half (16B) chunk id
                int r = f8 >> 3, cq = (f8 & 7) * 8;
                *(uint4*)&Ks[r * LDKH + cq] = *(const uint4*)(kp + r * DK + cq);
                *(uint4*)&Vt[r * LDKH + cq] = *(const uint4*)(vp + (size_t)r * TT + cq);
            }
        }
        __syncthreads();

        if (64 * j > rbase + 15) continue;   // warp fully above diagonal

        const uint32_t* Ks_u = (const uint32_t*)Ks;
        const uint32_t* Vt_u = (const uint32_t*)Vt;

        // ---- S = Q K^T ----
        float sa[8][4];
#pragma unroll
        for (int nt = 0; nt < 8; nt++) {
            sa[nt][0] = sa[nt][1] = sa[nt][2] = sa[nt][3] = 0.f;
#pragma unroll
            for (int kc = 0; kc < 4; kc++) {
                uint32_t b0 = Ks_u[(8 * nt + g) * (LDKH / 2) + 8 * kc + t];
                uint32_t b1 = Ks_u[(8 * nt + g) * (LDKH / 2) + 8 * kc + 4 + t];
                mma_f16(sa[nt], qf[kc], b0, b1);
            }
        }

        // ---- causal mask (diagonal region only) ----
        if (64 * j + 63 > rbase) {
            const int r0 = rbase + g, r1 = rbase + g + 8;
#pragma unroll
            for (int nt = 0; nt < 8; nt++) {
                int c0 = 64 * j + 8 * nt + 2 * t;
                if (c0 > r0)     sa[nt][0] = -1e30f;
                if (c0 + 1 > r0) sa[nt][1] = -1e30f;
                if (c0 > r1)     sa[nt][2] = -1e30f;
                if (c0 + 1 > r1) sa[nt][3] = -1e30f;
            }
        }

        // ---- online softmax (registers + quad shuffles) ----
        float mx0 = -1e30f, mx1 = -1e30f;
#pragma unroll
        for (int nt = 0; nt < 8; nt++) {
            mx0 = fmaxf(mx0, fmaxf(sa[nt][0], sa[nt][1]));
            mx1 = fmaxf(mx1, fmaxf(sa[nt][2], sa[nt][3]));
        }
        mx0 = fmaxf(mx0, __shfl_xor_sync(0xffffffffu, mx0, 1));
        mx0 = fmaxf(mx0, __shfl_xor_sync(0xffffffffu, mx0, 2));
        mx1 = fmaxf(mx1, __shfl_xor_sync(0xffffffffu, mx1, 1));
        mx1 = fmaxf(mx1, __shfl_xor_sync(0xffffffffu, mx1, 2));
        float mn0 = fmaxf(m0, mx0), mn1 = fmaxf(m1, mx1);
        float al0 = exp2f(m0 - mn0), al1 = exp2f(m1 - mn1);
        m0 = mn0; m1 = mn1;

        float sum0 = 0.f, sum1 = 0.f;
#pragma unroll
        for (int nt = 0; nt < 8; nt++) {
            float p0 = exp2f(sa[nt][0] - mn0);
            float p1 = exp2f(sa[nt][1] - mn0);
            float p2 = exp2f(sa[nt][2] - mn1);
            float p3 = exp2f(sa[nt][3] - mn1);
            sum0 += p0 + p1;
            sum1 += p2 + p3;
            sa[nt][0] = p0; sa[nt][1] = p1; sa[nt][2] = p2; sa[nt][3] = p3;
        }
        sum0 += __shfl_xor_sync(0xffffffffu, sum0, 1);
        sum0 += __shfl_xor_sync(0xffffffffu, sum0, 2);
        sum1 += __shfl_xor_sync(0xffffffffu, sum1, 1);
        sum1 += __shfl_xor_sync(0xffffffffu, sum1, 2);
        l0 = l0 * al0 + sum0;
        l1 = l1 * al1 + sum1;

#pragma unroll
        for (int dt = 0; dt < 8; dt++) {
            oa[dt][0] *= al0; oa[dt][1] *= al0;
            oa[dt][2] *= al1; oa[dt][3] *= al1;
        }

        // ---- pack P to fp16 A-fragments (pure registers: A-frag == C-frag) ----
        uint32_t pf[4][4];
#pragma unroll
        for (int kc = 0; kc < 4; kc++) {
            pf[kc][0] = pack_h2(sa[2 * kc][0],     sa[2 * kc][1]);      // (g, 16kc+2t:+1)
            pf[kc][1] = pack_h2(sa[2 * kc][2],     sa[2 * kc][3]);      // (g+8, ...)
            pf[kc][2] = pack_h2(sa[2 * kc + 1][0], sa[2 * kc + 1][1]);  // (g, 16kc+8+2t:+1)
            pf[kc][3] = pack_h2(sa[2 * kc + 1][2], sa[2 * kc + 1][3]);  // (g+8, ...)
        }

        // ---- O += P V ----
#pragma unroll
        for (int kc = 0; kc < 4; kc++) {
#pragma unroll
            for (int dt = 0; dt < 8; dt++) {
                uint32_t b0 = Vt_u[(8 * dt + g) * (LDKH / 2) + 8 * kc + t];
                uint32_t b1 = Vt_u[(8 * dt + g) * (LDKH / 2) + 8 * kc + 4 + t];
                mma_f16(oa[dt], pf[kc], b0, b1);
            }
        }
    }

    // ---- normalize & write [b*t][e] fp32 ----
    {
        float inv0 = 1.f / l0, inv1 = 1.f / l1;
        float* op0 = g_attn + (size_t)(bz * TT + rbase + g) * DMODEL + h * DK;
        float* op1 = g_attn + (size_t)(bz * TT + rbase + g + 8) * DMODEL + h * DK;
#pragma unroll
        for (int dt = 0; dt < 8; dt++) {
            *(float2*)&op0[8 * dt + 2 * t] = make_float2(oa[dt][0] * inv0, oa[dt][1] * inv0);
            *(float2*)&op1[8 * dt + 2 * t] = make_float2(oa[dt][2] * inv1, oa[dt][3] * inv1);
        }
    }
}

// ---------------------------------------------------------------------------
extern "C" void kernel_launch(void* const* d_in, const int* in_sizes, int n_in,
                              void* d_out, int out_size) {
    (void)in_sizes; (void)n_in; (void)out_size;
    const float* x  = (const float*)d_in[0];
    const float* Wq = (const float*)d_in[2];
    const float* Wk = (const float*)d_in[3];
    const float* Wv = (const float*)d_in[4];
    const float* Wo = (const float*)d_in[5];
    float* out = (float*)d_out;

    cudaFuncSetAttribute(flash_mma_kernel,
                         cudaFuncAttributeMaxDynamicSharedMemorySize, FLASH_SMEM);
    cudaFuncSetAttribute(gemm_mma_kernel<0>,
                         cudaFuncAttributeMaxDynamicSharedMemorySize, GEMM_SMEM);
    cudaFuncSetAttribute(gemm_mma_kernel<1>,
                         cudaFuncAttributeMaxDynamicSharedMemorySize, GEMM_SMEM);

    rope_table_kernel<<<(TT * 32 + 255) / 256, 256>>>();

    gemm_mma_kernel<0><<<dim3(MROWS / 128, 3072 / 128), 256, GEMM_SMEM>>>(
        x, Wq, Wk, Wv, nullptr);

    rope_apply_kernel<<<(2 * BB * NH * TT * 32 + 255) / 256, 256>>>();

    flash_mma_kernel<<<dim3(TT / 128, NH, BB), 256, FLASH_SMEM>>>();

    gemm_mma_kernel<1><<<dim3(MROWS / 128, DMODEL / 128), 256, GEMM_SMEM>>>(
        nullptr, Wo, nullptr, nullptr, out);
}